// round 7
// baseline (speedup 1.0000x reference)
#include <cuda_runtime.h>
#include <math.h>

#define NN 100000
#define NE 1000000
#define IN_CH 64
#define HID 128
#define NG 256

#define SCAN_BLOCKS 128
#define SCAN_CH ((NN + SCAN_BLOCKS - 1) / SCAN_BLOCKS)   // 782

// ---------------- scratch (device globals; no allocation) ----------------
__device__ int g_idx64;              // 1 if indices are int64, 0 if int32
__device__ int g_cnt[NN];
__device__ int g_row[NN];
__device__ int g_cur[NN];
__device__ float g_invdeg[NN];
__device__ int g_srcs[NE];
__device__ int g_blocksum[SCAN_BLOCKS];
__device__ __align__(16) float g_agg1[NN * IN_CH];   // 25.6 MB
__device__ __align__(16) float g_agg2[NN * HID];     // 51.2 MB
__device__ __align__(16) float g_h1[NN * HID];       // 51.2 MB
__device__ float g_pooled[NG * HID];

// index accessor honoring detected dtype
__device__ __forceinline__ int getidx(const void* p, long long i) {
    if (g_idx64) return (int)((const long long*)p)[i];
    return ((const int*)p)[i];
}

// ---------------- tf32 helpers ----------------
__device__ __forceinline__ unsigned f2tf(float f) {
    unsigned u;
    asm("cvt.rna.tf32.f32 %0, %1;" : "=r"(u) : "f"(f));
    return u;
}

__device__ __forceinline__ void mma_tf32(float* c, const unsigned* a, const unsigned* b) {
    asm volatile(
        "mma.sync.aligned.m16n8k8.row.col.f32.tf32.tf32.f32 "
        "{%0,%1,%2,%3},{%4,%5,%6,%7},{%8,%9},{%0,%1,%2,%3};"
        : "+f"(c[0]), "+f"(c[1]), "+f"(c[2]), "+f"(c[3])
        : "r"(a[0]), "r"(a[1]), "r"(a[2]), "r"(a[3]), "r"(b[0]), "r"(b[1]));
}

// ---------------- dtype probe ----------------
__global__ void probe_dtype(const unsigned long long* __restrict__ ei) {
    if (threadIdx.x == 0 && blockIdx.x == 0) {
        int is64 = 1;
        for (int i = 0; i < 16; i++)
            if (ei[i] >> 32) is64 = 0;
        g_idx64 = is64;
    }
}

// ---------------- zero counters + pooled ----------------
__global__ void zero_small() {
    int i = blockIdx.x * blockDim.x + threadIdx.x;
    int stride = gridDim.x * blockDim.x;
    for (int j = i; j < NN; j += stride) g_cnt[j] = 0;
    for (int j = i; j < NG * HID; j += stride) g_pooled[j] = 0.f;
}

// ---------------- histogram of dst degrees ----------------
__global__ void __launch_bounds__(256) hist(const void* __restrict__ ei) {
    int e = blockIdx.x * blockDim.x + threadIdx.x;
    if (e >= NE) return;
    int dst = getidx(ei, NE + e);
    atomicAdd(&g_cnt[dst], 1);
}

// ---------------- 3-phase scan ----------------
__global__ void __launch_bounds__(256) scan_p1() {
    __shared__ int sb[256];
    int b = blockIdx.x, t = threadIdx.x;
    int base = b * SCAN_CH;
    int end = min(base + SCAN_CH, NN);
    int s = 0;
    for (int idx = base + t; idx < end; idx += 256) s += g_cnt[idx];
    sb[t] = s;
    __syncthreads();
    for (int off = 128; off > 0; off >>= 1) {
        if (t < off) sb[t] += sb[t + off];
        __syncthreads();
    }
    if (t == 0) g_blocksum[b] = sb[0];
}

__global__ void __launch_bounds__(128) scan_p2() {
    __shared__ int sb[128];
    int t = threadIdx.x;
    int v = g_blocksum[t];
    sb[t] = v;
    __syncthreads();
    for (int off = 1; off < 128; off <<= 1) {
        int u = (t >= off) ? sb[t - off] : 0;
        __syncthreads();
        sb[t] += u;
        __syncthreads();
    }
    g_blocksum[t] = sb[t] - v;   // exclusive
}

__global__ void __launch_bounds__(256) scan_p3() {
    __shared__ int sb[256];
    __shared__ int s_off;
    int b = blockIdx.x, t = threadIdx.x;
    int base = b * SCAN_CH;
    int end = min(base + SCAN_CH, NN);
    if (t == 0) s_off = g_blocksum[b];
    __syncthreads();
    for (int tile = base; tile < end; tile += 256) {
        int idx = tile + t;
        int c = (idx < end) ? g_cnt[idx] : 0;
        sb[t] = c;
        __syncthreads();
        for (int off = 1; off < 256; off <<= 1) {
            int u = (t >= off) ? sb[t - off] : 0;
            __syncthreads();
            sb[t] += u;
            __syncthreads();
        }
        int incl = sb[t];
        int excl = incl - c;
        if (idx < end) {
            int r = s_off + excl;
            g_row[idx] = r;
            g_cur[idx] = r;
            g_invdeg[idx] = 1.0f / fmaxf((float)c, 1.0f);
        }
        __syncthreads();
        if (t == 255) s_off += sb[255];
        __syncthreads();
    }
}

// ---------------- fill CSR src lists ----------------
__global__ void __launch_bounds__(256) fill_csr(const void* __restrict__ ei) {
    int e = blockIdx.x * blockDim.x + threadIdx.x;
    if (e >= NE) return;
    int dst = getidx(ei, NE + e);
    int src = getidx(ei, e);
    int pos = atomicAdd(&g_cur[dst], 1);
    g_srcs[pos] = src;
}

// ---------------- gather-mean layer 1 (64 ch) ----------------
__global__ void __launch_bounds__(256) gather1(const float4* __restrict__ x4) {
    unsigned t = blockIdx.x * blockDim.x + threadIdx.x;
    unsigned n = t >> 4, q = t & 15;
    if (n >= NN) return;
    int start = g_row[n];
    int cnt = g_cnt[n];
    float inv = g_invdeg[n];
    float4 acc = make_float4(0.f, 0.f, 0.f, 0.f);
    for (int j = 0; j < cnt; j++) {
        int s = g_srcs[start + j];
        float4 v = x4[(size_t)s * 16 + q];
        acc.x += v.x; acc.y += v.y; acc.z += v.z; acc.w += v.w;
    }
    acc.x *= inv; acc.y *= inv; acc.z *= inv; acc.w *= inv;
    ((float4*)g_agg1)[(size_t)n * 16 + q] = acc;
}

// ---------------- gather-mean layer 2 (128 ch) ----------------
__global__ void __launch_bounds__(256) gather2() {
    unsigned t = blockIdx.x * blockDim.x + threadIdx.x;
    unsigned n = t >> 5, q = t & 31;
    if (n >= NN) return;
    int start = g_row[n];
    int cnt = g_cnt[n];
    float inv = g_invdeg[n];
    const float4* h4 = (const float4*)g_h1;
    float4 acc = make_float4(0.f, 0.f, 0.f, 0.f);
    for (int j = 0; j < cnt; j++) {
        int s = g_srcs[start + j];
        float4 v = h4[(size_t)s * 32 + q];
        acc.x += v.x; acc.y += v.y; acc.z += v.z; acc.w += v.w;
    }
    acc.x *= inv; acc.y *= inv; acc.z *= inv; acc.w *= inv;
    ((float4*)g_agg2)[(size_t)n * 32 + q] = acc;
}

// ---------------- tensor-core fused SAGE GEMM (3xTF32, smem-preconverted hi/lo) ----------------
// out[n, c] = relu( agg[n] @ W0^T + feat[n] @ W1^T + bias )   (agg pre-normalized)
// Block tile: 128 nodes x 128 ch, 256 threads = 8 warps (4 M x 2 N).
// hi/lo tf32 split converted ONCE per element at tile-load time into smem.
// Inner loop: pure LDS + MMA (no cvt). Register prefetch of next gmem tile.
template <int K, bool DO_POOL>
__device__ __forceinline__ void tc_gemm_body(
    const float* __restrict__ agg, const float* __restrict__ feat,
    const float* __restrict__ W0, const float* __restrict__ W1,
    const float* __restrict__ bias, float* __restrict__ out,
    const void* __restrict__ batch) {
    constexpr int KH = K / 2;
    __shared__ unsigned Ah[128][20], Al[128][20];
    __shared__ unsigned Bh[128][20], Bl[128][20];

    int tid = threadIdx.x;
    int lane = tid & 31, wid = tid >> 5;
    int warpM = wid & 3, warpN = wid >> 2;
    int g = lane >> 2, c = lane & 3;
    int m0 = blockIdx.x * 128;

    int lrow = tid >> 1;             // 0..127
    int lhalf = (tid & 1) * 8;       // 0 or 8

    float acc[2][8][4];
#pragma unroll
    for (int mt = 0; mt < 2; mt++)
#pragma unroll
        for (int nt = 0; nt < 8; nt++)
#pragma unroll
            for (int i = 0; i < 4; i++) acc[mt][nt][i] = 0.f;

    int node_l = m0 + lrow;
    bool av = node_l < NN;

    float a_reg[8], b_reg[8];
    // ---- load tile 0 into registers ----
    {
        int kg = lhalf;  // kk = 0
        float4 v0 = make_float4(0.f, 0.f, 0.f, 0.f), v1 = v0;
        if (av) {
            const float* base = (kg < KH) ? (agg + (size_t)node_l * KH + kg)
                                          : (feat + (size_t)node_l * KH + (kg - KH));
            v0 = *(const float4*)base;
            v1 = *(const float4*)(base + 4);
        }
        a_reg[0] = v0.x; a_reg[1] = v0.y; a_reg[2] = v0.z; a_reg[3] = v0.w;
        a_reg[4] = v1.x; a_reg[5] = v1.y; a_reg[6] = v1.z; a_reg[7] = v1.w;
        const float* wb = (kg < KH) ? (W0 + (size_t)lrow * KH + kg)
                                    : (W1 + (size_t)lrow * KH + (kg - KH));
        float4 w0 = *(const float4*)wb;
        float4 w1 = *(const float4*)(wb + 4);
        b_reg[0] = w0.x; b_reg[1] = w0.y; b_reg[2] = w0.z; b_reg[3] = w0.w;
        b_reg[4] = w1.x; b_reg[5] = w1.y; b_reg[6] = w1.z; b_reg[7] = w1.w;
    }

    for (int kk = 0; kk < K; kk += 16) {
        // ---- convert + store current regs into smem (hi/lo) ----
        {
            unsigned h[8], l[8];
#pragma unroll
            for (int i = 0; i < 8; i++) {
                h[i] = f2tf(a_reg[i]);
                l[i] = f2tf(a_reg[i] - __uint_as_float(h[i]));
            }
            *(uint4*)&Ah[lrow][lhalf] = make_uint4(h[0], h[1], h[2], h[3]);
            *(uint4*)&Ah[lrow][lhalf + 4] = make_uint4(h[4], h[5], h[6], h[7]);
            *(uint4*)&Al[lrow][lhalf] = make_uint4(l[0], l[1], l[2], l[3]);
            *(uint4*)&Al[lrow][lhalf + 4] = make_uint4(l[4], l[5], l[6], l[7]);
#pragma unroll
            for (int i = 0; i < 8; i++) {
                h[i] = f2tf(b_reg[i]);
                l[i] = f2tf(b_reg[i] - __uint_as_float(h[i]));
            }
            *(uint4*)&Bh[lrow][lhalf] = make_uint4(h[0], h[1], h[2], h[3]);
            *(uint4*)&Bh[lrow][lhalf + 4] = make_uint4(h[4], h[5], h[6], h[7]);
            *(uint4*)&Bl[lrow][lhalf] = make_uint4(l[0], l[1], l[2], l[3]);
            *(uint4*)&Bl[lrow][lhalf + 4] = make_uint4(l[4], l[5], l[6], l[7]);
        }
        __syncthreads();

        // ---- prefetch next tile into registers (latency hidden by MMA loop) ----
        if (kk + 16 < K) {
            int kg = kk + 16 + lhalf;
            float4 v0 = make_float4(0.f, 0.f, 0.f, 0.f), v1 = v0;
            if (av) {
                const float* base = (kg < KH) ? (agg + (size_t)node_l * KH + kg)
                                              : (feat + (size_t)node_l * KH + (kg - KH));
                v0 = *(const float4*)base;
                v1 = *(const float4*)(base + 4);
            }
            a_reg[0] = v0.x; a_reg[1] = v0.y; a_reg[2] = v0.z; a_reg[3] = v0.w;
            a_reg[4] = v1.x; a_reg[5] = v1.y; a_reg[6] = v1.z; a_reg[7] = v1.w;
            const float* wb = (kg < KH) ? (W0 + (size_t)lrow * KH + kg)
                                        : (W1 + (size_t)lrow * KH + (kg - KH));
            float4 w0 = *(const float4*)wb;
            float4 w1 = *(const float4*)(wb + 4);
            b_reg[0] = w0.x; b_reg[1] = w0.y; b_reg[2] = w0.z; b_reg[3] = w0.w;
            b_reg[4] = w1.x; b_reg[5] = w1.y; b_reg[6] = w1.z; b_reg[7] = w1.w;
        }

        // ---- compute: pure LDS + MMA ----
#pragma unroll
        for (int k8 = 0; k8 < 16; k8 += 8) {
            unsigned ah[2][4], al[2][4];
#pragma unroll
            for (int mt = 0; mt < 2; mt++) {
                int rb = warpM * 32 + mt * 16;
                ah[mt][0] = Ah[rb + g][k8 + c];
                ah[mt][1] = Ah[rb + g + 8][k8 + c];
                ah[mt][2] = Ah[rb + g][k8 + c + 4];
                ah[mt][3] = Ah[rb + g + 8][k8 + c + 4];
                al[mt][0] = Al[rb + g][k8 + c];
                al[mt][1] = Al[rb + g + 8][k8 + c];
                al[mt][2] = Al[rb + g][k8 + c + 4];
                al[mt][3] = Al[rb + g + 8][k8 + c + 4];
            }
#pragma unroll
            for (int nt = 0; nt < 8; nt++) {
                int nb = warpN * 64 + nt * 8;
                unsigned bh[2], bl[2];
                bh[0] = Bh[nb + g][k8 + c];
                bh[1] = Bh[nb + g][k8 + c + 4];
                bl[0] = Bl[nb + g][k8 + c];
                bl[1] = Bl[nb + g][k8 + c + 4];
#pragma unroll
                for (int mt = 0; mt < 2; mt++) {
                    mma_tf32(acc[mt][nt], ah[mt], bh);   // hi*hi
                    mma_tf32(acc[mt][nt], ah[mt], bl);   // hi*lo
                    mma_tf32(acc[mt][nt], al[mt], bh);   // lo*hi
                }
            }
        }
        __syncthreads();
    }

    // ---- epilogue: bias + relu, then store or pool ----
#pragma unroll
    for (int mt = 0; mt < 2; mt++) {
        int r0 = m0 + warpM * 32 + mt * 16 + g;
        int r1 = r0 + 8;
#pragma unroll
        for (int nt = 0; nt < 8; nt++) {
            int col = warpN * 64 + nt * 8 + 2 * c;
            float b0 = bias[col], b1 = bias[col + 1];
            float v00 = fmaxf(acc[mt][nt][0] + b0, 0.f);
            float v01 = fmaxf(acc[mt][nt][1] + b1, 0.f);
            float v10 = fmaxf(acc[mt][nt][2] + b0, 0.f);
            float v11 = fmaxf(acc[mt][nt][3] + b1, 0.f);
            if (DO_POOL) {
                if (r0 < NN) {
                    float* p = g_pooled + (size_t)getidx(batch, r0) * HID + col;
                    atomicAdd(p, v00);
                    atomicAdd(p + 1, v01);
                }
                if (r1 < NN) {
                    float* p = g_pooled + (size_t)getidx(batch, r1) * HID + col;
                    atomicAdd(p, v10);
                    atomicAdd(p + 1, v11);
                }
            } else {
                if (r0 < NN) *(float2*)(out + (size_t)r0 * HID + col) = make_float2(v00, v01);
                if (r1 < NN) *(float2*)(out + (size_t)r1 * HID + col) = make_float2(v10, v11);
            }
        }
    }
}

__global__ void __launch_bounds__(256) tc_gemm_l1(
    const float* __restrict__ x, const float* __restrict__ W0,
    const float* __restrict__ W1, const float* __restrict__ bias) {
    tc_gemm_body<2 * IN_CH, false>(g_agg1, x, W0, W1, bias, g_h1, nullptr);
}

__global__ void __launch_bounds__(256) tc_gemm_l2(
    const float* __restrict__ W0, const float* __restrict__ W1,
    const float* __restrict__ bias, const void* __restrict__ batch) {
    tc_gemm_body<2 * HID, true>(g_agg2, g_h1, W0, W1, bias, nullptr, batch);
}

// ---------------- finalize: per-graph mean, Wout, log_softmax ----------------
__global__ void __launch_bounds__(256) finalize(const void* __restrict__ batch,
                                                const float* __restrict__ Wout,
                                                const float* __restrict__ bout,
                                                float* __restrict__ outp) {
    int g = threadIdx.x;
    auto lower_bound = [&](int v) {
        int lo = 0, hi = NN;
        while (lo < hi) {
            int mid = (lo + hi) >> 1;
            if (getidx(batch, mid) < v) lo = mid + 1; else hi = mid;
        }
        return lo;
    };
    int cnt = lower_bound(g + 1) - lower_bound(g);
    float inv = 1.0f / fmaxf((float)cnt, 1.0f);
    float l0 = bout[0], l1 = bout[1];
    for (int c = 0; c < HID; c++) {
        float p = g_pooled[(size_t)g * HID + c] * inv;
        l0 += p * Wout[c];
        l1 += p * Wout[HID + c];
    }
    float m = fmaxf(l0, l1);
    float lse = m + logf(expf(l0 - m) + expf(l1 - m));
    outp[g * 2 + 0] = l0 - lse;
    outp[g * 2 + 1] = l1 - lse;
}

// ---------------- launch ----------------
extern "C" void kernel_launch(void* const* d_in, const int* in_sizes, int n_in,
                              void* d_out, int out_size) {
    const float* x = (const float*)d_in[0];
    const void* ei = d_in[1];
    const void* batch = d_in[2];
    const float* Wl1 = (const float*)d_in[3];
    const float* bl1 = (const float*)d_in[4];
    const float* Wr1 = (const float*)d_in[5];
    const float* Wl2 = (const float*)d_in[6];
    const float* bl2 = (const float*)d_in[7];
    const float* Wr2 = (const float*)d_in[8];
    const float* Wout = (const float*)d_in[9];
    const float* bout = (const float*)d_in[10];
    float* out = (float*)d_out;

    int eb = (NE + 255) / 256;
    int gemm_blocks = (NN + 127) / 128;

    probe_dtype<<<1, 32>>>((const unsigned long long*)ei);
    zero_small<<<256, 256>>>();
    hist<<<eb, 256>>>(ei);
    scan_p1<<<SCAN_BLOCKS, 256>>>();
    scan_p2<<<1, 128>>>();
    scan_p3<<<SCAN_BLOCKS, 256>>>();
    fill_csr<<<eb, 256>>>(ei);

    gather1<<<(NN * 16 + 255) / 256, 256>>>((const float4*)x);
    tc_gemm_l1<<<gemm_blocks, 256>>>(x, Wl1, Wr1, bl1);
    gather2<<<(NN * 32 + 255) / 256, 256>>>();
    tc_gemm_l2<<<gemm_blocks, 256>>>(Wl2, Wr2, bl2, batch);
    finalize<<<1, 256>>>(batch, Wout, bout, out);
}

// round 9
// speedup vs baseline: 1.4153x; 1.4153x over previous
#include <cuda_runtime.h>
#include <math.h>

#define NN 100000
#define NE 1000000
#define IN_CH 64
#define HID 128
#define NG 256

#define SCAN_BLOCKS 128
#define SCAN_CH ((NN + SCAN_BLOCKS - 1) / SCAN_BLOCKS)   // 782

// ---------------- scratch (device globals; no allocation) ----------------
__device__ int g_idx64;              // 1 if indices are int64, 0 if int32
__device__ int g_cnt[NN];
__device__ int g_row[NN];
__device__ int g_cur[NN];
__device__ float g_invdeg[NN];
__device__ int g_srcs[NE];
__device__ int g_blocksum[SCAN_BLOCKS];
__device__ __align__(16) float g_agg1[NN * IN_CH];   // 25.6 MB
__device__ __align__(16) float g_agg2[NN * HID];     // 51.2 MB
__device__ __align__(16) float g_h1[NN * HID];       // 51.2 MB
__device__ float g_pooled[NG * HID];

// index accessor honoring detected dtype
__device__ __forceinline__ int getidx(const void* p, long long i) {
    if (g_idx64) return (int)((const long long*)p)[i];
    return ((const int*)p)[i];
}

// ---------------- bf16 helpers ----------------
// pack two floats into bf16x2: low half = lo-arg, high half = hi-arg
__device__ __forceinline__ unsigned pack_bf16x2(float lo, float hi) {
    unsigned r;
    asm("cvt.rn.bf16x2.f32 %0, %1, %2;" : "=r"(r) : "f"(hi), "f"(lo));
    return r;
}

__device__ __forceinline__ void mma_bf16(float* c, const unsigned* a, const unsigned* b) {
    asm volatile(
        "mma.sync.aligned.m16n8k16.row.col.f32.bf16.bf16.f32 "
        "{%0,%1,%2,%3},{%4,%5,%6,%7},{%8,%9},{%0,%1,%2,%3};"
        : "+f"(c[0]), "+f"(c[1]), "+f"(c[2]), "+f"(c[3])
        : "r"(a[0]), "r"(a[1]), "r"(a[2]), "r"(a[3]), "r"(b[0]), "r"(b[1]));
}

// convert 8 consecutive floats into 4 packed hi-words + 4 packed lo-words
__device__ __forceinline__ void split_bf16_8(const float* v, unsigned* hp, unsigned* lp) {
#pragma unroll
    for (int j = 0; j < 4; j++) {
        float a0 = v[2 * j], a1 = v[2 * j + 1];
        unsigned h = pack_bf16x2(a0, a1);
        float h0 = __uint_as_float(h << 16);
        float h1 = __uint_as_float(h & 0xffff0000u);
        hp[j] = h;
        lp[j] = pack_bf16x2(a0 - h0, a1 - h1);
    }
}

// ---------------- dtype probe ----------------
__global__ void probe_dtype(const unsigned long long* __restrict__ ei) {
    if (threadIdx.x == 0 && blockIdx.x == 0) {
        int is64 = 1;
        for (int i = 0; i < 16; i++)
            if (ei[i] >> 32) is64 = 0;
        g_idx64 = is64;
    }
}

// ---------------- zero counters + pooled ----------------
__global__ void zero_small() {
    int i = blockIdx.x * blockDim.x + threadIdx.x;
    int stride = gridDim.x * blockDim.x;
    for (int j = i; j < NN; j += stride) g_cnt[j] = 0;
    for (int j = i; j < NG * HID; j += stride) g_pooled[j] = 0.f;
}

// ---------------- histogram of dst degrees ----------------
__global__ void __launch_bounds__(256) hist(const void* __restrict__ ei) {
    int e = blockIdx.x * blockDim.x + threadIdx.x;
    if (e >= NE) return;
    int dst = getidx(ei, NE + e);
    atomicAdd(&g_cnt[dst], 1);
}

// ---------------- 3-phase scan ----------------
__global__ void __launch_bounds__(256) scan_p1() {
    __shared__ int sb[256];
    int b = blockIdx.x, t = threadIdx.x;
    int base = b * SCAN_CH;
    int end = min(base + SCAN_CH, NN);
    int s = 0;
    for (int idx = base + t; idx < end; idx += 256) s += g_cnt[idx];
    sb[t] = s;
    __syncthreads();
    for (int off = 128; off > 0; off >>= 1) {
        if (t < off) sb[t] += sb[t + off];
        __syncthreads();
    }
    if (t == 0) g_blocksum[b] = sb[0];
}

__global__ void __launch_bounds__(128) scan_p2() {
    __shared__ int sb[128];
    int t = threadIdx.x;
    int v = g_blocksum[t];
    sb[t] = v;
    __syncthreads();
    for (int off = 1; off < 128; off <<= 1) {
        int u = (t >= off) ? sb[t - off] : 0;
        __syncthreads();
        sb[t] += u;
        __syncthreads();
    }
    g_blocksum[t] = sb[t] - v;   // exclusive
}

__global__ void __launch_bounds__(256) scan_p3() {
    __shared__ int sb[256];
    __shared__ int s_off;
    int b = blockIdx.x, t = threadIdx.x;
    int base = b * SCAN_CH;
    int end = min(base + SCAN_CH, NN);
    if (t == 0) s_off = g_blocksum[b];
    __syncthreads();
    for (int tile = base; tile < end; tile += 256) {
        int idx = tile + t;
        int c = (idx < end) ? g_cnt[idx] : 0;
        sb[t] = c;
        __syncthreads();
        for (int off = 1; off < 256; off <<= 1) {
            int u = (t >= off) ? sb[t - off] : 0;
            __syncthreads();
            sb[t] += u;
            __syncthreads();
        }
        int incl = sb[t];
        int excl = incl - c;
        if (idx < end) {
            int r = s_off + excl;
            g_row[idx] = r;
            g_cur[idx] = r;
            g_invdeg[idx] = 1.0f / fmaxf((float)c, 1.0f);
        }
        __syncthreads();
        if (t == 255) s_off += sb[255];
        __syncthreads();
    }
}

// ---------------- fill CSR src lists ----------------
__global__ void __launch_bounds__(256) fill_csr(const void* __restrict__ ei) {
    int e = blockIdx.x * blockDim.x + threadIdx.x;
    if (e >= NE) return;
    int dst = getidx(ei, NE + e);
    int src = getidx(ei, e);
    int pos = atomicAdd(&g_cur[dst], 1);
    g_srcs[pos] = src;
}

// ---------------- gather-mean layer 1 (64 ch) ----------------
__global__ void __launch_bounds__(256) gather1(const float4* __restrict__ x4) {
    unsigned t = blockIdx.x * blockDim.x + threadIdx.x;
    unsigned n = t >> 4, q = t & 15;
    if (n >= NN) return;
    int start = g_row[n];
    int cnt = g_cnt[n];
    float inv = g_invdeg[n];
    float4 acc = make_float4(0.f, 0.f, 0.f, 0.f);
    for (int j = 0; j < cnt; j++) {
        int s = g_srcs[start + j];
        float4 v = x4[(size_t)s * 16 + q];
        acc.x += v.x; acc.y += v.y; acc.z += v.z; acc.w += v.w;
    }
    acc.x *= inv; acc.y *= inv; acc.z *= inv; acc.w *= inv;
    ((float4*)g_agg1)[(size_t)n * 16 + q] = acc;
}

// ---------------- gather-mean layer 2 (128 ch) ----------------
__global__ void __launch_bounds__(256) gather2() {
    unsigned t = blockIdx.x * blockDim.x + threadIdx.x;
    unsigned n = t >> 5, q = t & 31;
    if (n >= NN) return;
    int start = g_row[n];
    int cnt = g_cnt[n];
    float inv = g_invdeg[n];
    const float4* h4 = (const float4*)g_h1;
    float4 acc = make_float4(0.f, 0.f, 0.f, 0.f);
    for (int j = 0; j < cnt; j++) {
        int s = g_srcs[start + j];
        float4 v = h4[(size_t)s * 32 + q];
        acc.x += v.x; acc.y += v.y; acc.z += v.z; acc.w += v.w;
    }
    acc.x *= inv; acc.y *= inv; acc.z *= inv; acc.w *= inv;
    ((float4*)g_agg2)[(size_t)n * 32 + q] = acc;
}

// ---------------- tensor-core fused SAGE GEMM (3xBF16 m16n8k16) ----------------
// out[n, c] = relu( agg[n] @ W0^T + feat[n] @ W1^T + bias )   (agg pre-normalized)
// Block tile: 128 nodes x 128 ch, 256 threads = 8 warps (4 M x 2 N).
// bf16 hi/lo split done once at tile load; packed bf16x2 along k so one LDS.32
// fetches a whole fragment register. Inner loop: 48 LDS + 48 MMA per k16 tile.
// smem stride 12 uints: (12g + c) mod 32 covers all banks -> conflict-free.
template <int K, bool DO_POOL>
__device__ __forceinline__ void tc_gemm_body(
    const float* __restrict__ agg, const float* __restrict__ feat,
    const float* __restrict__ W0, const float* __restrict__ W1,
    const float* __restrict__ bias, float* __restrict__ out,
    const void* __restrict__ batch) {
    constexpr int KH = K / 2;
    __shared__ unsigned Ah[128][12], Al[128][12];   // [row][kpair]
    __shared__ unsigned Bh[128][12], Bl[128][12];   // [outch][kpair]

    int tid = threadIdx.x;
    int lane = tid & 31, wid = tid >> 5;
    int warpM = wid & 3, warpN = wid >> 2;
    int g = lane >> 2, c = lane & 3;
    int m0 = blockIdx.x * 128;

    int lrow = tid >> 1;             // 0..127
    int lhalf = (tid & 1) * 8;       // float offset 0 or 8
    int lkp = (tid & 1) * 4;         // kpair offset 0 or 4

    float acc[2][8][4];
#pragma unroll
    for (int mt = 0; mt < 2; mt++)
#pragma unroll
        for (int nt = 0; nt < 8; nt++)
#pragma unroll
            for (int i = 0; i < 4; i++) acc[mt][nt][i] = 0.f;

    int node_l = m0 + lrow;
    bool av = node_l < NN;

    float a_reg[8], b_reg[8];
    // ---- load tile 0 into registers ----
    {
        int kg = lhalf;
        float4 v0 = make_float4(0.f, 0.f, 0.f, 0.f), v1 = v0;
        if (av) {
            const float* base = (kg < KH) ? (agg + (size_t)node_l * KH + kg)
                                          : (feat + (size_t)node_l * KH + (kg - KH));
            v0 = *(const float4*)base;
            v1 = *(const float4*)(base + 4);
        }
        a_reg[0] = v0.x; a_reg[1] = v0.y; a_reg[2] = v0.z; a_reg[3] = v0.w;
        a_reg[4] = v1.x; a_reg[5] = v1.y; a_reg[6] = v1.z; a_reg[7] = v1.w;
        const float* wb = (kg < KH) ? (W0 + (size_t)lrow * KH + kg)
                                    : (W1 + (size_t)lrow * KH + (kg - KH));
        float4 w0 = *(const float4*)wb;
        float4 w1 = *(const float4*)(wb + 4);
        b_reg[0] = w0.x; b_reg[1] = w0.y; b_reg[2] = w0.z; b_reg[3] = w0.w;
        b_reg[4] = w1.x; b_reg[5] = w1.y; b_reg[6] = w1.z; b_reg[7] = w1.w;
    }

    for (int kk = 0; kk < K; kk += 16) {
        // ---- convert current regs -> packed bf16 hi/lo in smem ----
        {
            unsigned hp[4], lp[4];
            split_bf16_8(a_reg, hp, lp);
            *(uint4*)&Ah[lrow][lkp] = make_uint4(hp[0], hp[1], hp[2], hp[3]);
            *(uint4*)&Al[lrow][lkp] = make_uint4(lp[0], lp[1], lp[2], lp[3]);
            split_bf16_8(b_reg, hp, lp);
            *(uint4*)&Bh[lrow][lkp] = make_uint4(hp[0], hp[1], hp[2], hp[3]);
            *(uint4*)&Bl[lrow][lkp] = make_uint4(lp[0], lp[1], lp[2], lp[3]);
        }
        __syncthreads();

        // ---- prefetch next tile into registers ----
        if (kk + 16 < K) {
            int kg = kk + 16 + lhalf;
            float4 v0 = make_float4(0.f, 0.f, 0.f, 0.f), v1 = v0;
            if (av) {
                const float* base = (kg < KH) ? (agg + (size_t)node_l * KH + kg)
                                              : (feat + (size_t)node_l * KH + (kg - KH));
                v0 = *(const float4*)base;
                v1 = *(const float4*)(base + 4);
            }
            a_reg[0] = v0.x; a_reg[1] = v0.y; a_reg[2] = v0.z; a_reg[3] = v0.w;
            a_reg[4] = v1.x; a_reg[5] = v1.y; a_reg[6] = v1.z; a_reg[7] = v1.w;
            const float* wb = (kg < KH) ? (W0 + (size_t)lrow * KH + kg)
                                        : (W1 + (size_t)lrow * KH + (kg - KH));
            float4 w0 = *(const float4*)wb;
            float4 w1 = *(const float4*)(wb + 4);
            b_reg[0] = w0.x; b_reg[1] = w0.y; b_reg[2] = w0.z; b_reg[3] = w0.w;
            b_reg[4] = w1.x; b_reg[5] = w1.y; b_reg[6] = w1.z; b_reg[7] = w1.w;
        }

        // ---- compute: one m16n8k16 step covers the whole 16-k tile ----
        {
            unsigned ah[2][4], al[2][4];
#pragma unroll
            for (int mt = 0; mt < 2; mt++) {
                int rb = warpM * 32 + mt * 16;
                ah[mt][0] = Ah[rb + g][c];
                ah[mt][1] = Ah[rb + g + 8][c];
                ah[mt][2] = Ah[rb + g][c + 4];
                ah[mt][3] = Ah[rb + g + 8][c + 4];
                al[mt][0] = Al[rb + g][c];
                al[mt][1] = Al[rb + g + 8][c];
                al[mt][2] = Al[rb + g][c + 4];
                al[mt][3] = Al[rb + g + 8][c + 4];
            }
#pragma unroll
            for (int nt = 0; nt < 8; nt++) {
                int nb = warpN * 64 + nt * 8;
                unsigned bh[2], bl[2];
                bh[0] = Bh[nb + g][c];
                bh[1] = Bh[nb + g][c + 4];
                bl[0] = Bl[nb + g][c];
                bl[1] = Bl[nb + g][c + 4];
#pragma unroll
                for (int mt = 0; mt < 2; mt++) {
                    mma_bf16(acc[mt][nt], ah[mt], bh);   // hi*hi
                    mma_bf16(acc[mt][nt], ah[mt], bl);   // hi*lo
                    mma_bf16(acc[mt][nt], al[mt], bh);   // lo*hi
                }
            }
        }
        __syncthreads();
    }

    // ---- epilogue: bias + relu, then store or pool ----
#pragma unroll
    for (int mt = 0; mt < 2; mt++) {
        int r0 = m0 + warpM * 32 + mt * 16 + g;
        int r1 = r0 + 8;
#pragma unroll
        for (int nt = 0; nt < 8; nt++) {
            int col = warpN * 64 + nt * 8 + 2 * c;
            float b0 = bias[col], b1 = bias[col + 1];
            float v00 = fmaxf(acc[mt][nt][0] + b0, 0.f);
            float v01 = fmaxf(acc[mt][nt][1] + b1, 0.f);
            float v10 = fmaxf(acc[mt][nt][2] + b0, 0.f);
            float v11 = fmaxf(acc[mt][nt][3] + b1, 0.f);
            if (DO_POOL) {
                if (r0 < NN) {
                    float* p = g_pooled + (size_t)getidx(batch, r0) * HID + col;
                    atomicAdd(p, v00);
                    atomicAdd(p + 1, v01);
                }
                if (r1 < NN) {
                    float* p = g_pooled + (size_t)getidx(batch, r1) * HID + col;
                    atomicAdd(p, v10);
                    atomicAdd(p + 1, v11);
                }
            } else {
                if (r0 < NN) *(float2*)(out + (size_t)r0 * HID + col) = make_float2(v00, v01);
                if (r1 < NN) *(float2*)(out + (size_t)r1 * HID + col) = make_float2(v10, v11);
            }
        }
    }
}

__global__ void __launch_bounds__(256) tc_gemm_l1(
    const float* __restrict__ x, const float* __restrict__ W0,
    const float* __restrict__ W1, const float* __restrict__ bias) {
    tc_gemm_body<2 * IN_CH, false>(g_agg1, x, W0, W1, bias, g_h1, nullptr);
}

__global__ void __launch_bounds__(256) tc_gemm_l2(
    const float* __restrict__ W0, const float* __restrict__ W1,
    const float* __restrict__ bias, const void* __restrict__ batch) {
    tc_gemm_body<2 * HID, true>(g_agg2, g_h1, W0, W1, bias, nullptr, batch);
}

// ---------------- finalize: per-graph mean, Wout, log_softmax ----------------
__global__ void __launch_bounds__(256) finalize(const void* __restrict__ batch,
                                                const float* __restrict__ Wout,
                                                const float* __restrict__ bout,
                                                float* __restrict__ outp) {
    int g = threadIdx.x;
    auto lower_bound = [&](int v) {
        int lo = 0, hi = NN;
        while (lo < hi) {
            int mid = (lo + hi) >> 1;
            if (getidx(batch, mid) < v) lo = mid + 1; else hi = mid;
        }
        return lo;
    };
    int cnt = lower_bound(g + 1) - lower_bound(g);
    float inv = 1.0f / fmaxf((float)cnt, 1.0f);
    float l0 = bout[0], l1 = bout[1];
    for (int c = 0; c < HID; c++) {
        float p = g_pooled[(size_t)g * HID + c] * inv;
        l0 += p * Wout[c];
        l1 += p * Wout[HID + c];
    }
    float m = fmaxf(l0, l1);
    float lse = m + logf(expf(l0 - m) + expf(l1 - m));
    outp[g * 2 + 0] = l0 - lse;
    outp[g * 2 + 1] = l1 - lse;
}

// ---------------- launch ----------------
extern "C" void kernel_launch(void* const* d_in, const int* in_sizes, int n_in,
                              void* d_out, int out_size) {
    const float* x = (const float*)d_in[0];
    const void* ei = d_in[1];
    const void* batch = d_in[2];
    const float* Wl1 = (const float*)d_in[3];
    const float* bl1 = (const float*)d_in[4];
    const float* Wr1 = (const float*)d_in[5];
    const float* Wl2 = (const float*)d_in[6];
    const float* bl2 = (const float*)d_in[7];
    const float* Wr2 = (const float*)d_in[8];
    const float* Wout = (const float*)d_in[9];
    const float* bout = (const float*)d_in[10];
    float* out = (float*)d_out;

    int eb = (NE + 255) / 256;
    int gemm_blocks = (NN + 127) / 128;

    probe_dtype<<<1, 32>>>((const unsigned long long*)ei);
    zero_small<<<256, 256>>>();
    hist<<<eb, 256>>>(ei);
    scan_p1<<<SCAN_BLOCKS, 256>>>();
    scan_p2<<<1, 128>>>();
    scan_p3<<<SCAN_BLOCKS, 256>>>();
    fill_csr<<<eb, 256>>>(ei);

    gather1<<<(NN * 16 + 255) / 256, 256>>>((const float4*)x);
    tc_gemm_l1<<<gemm_blocks, 256>>>(x, Wl1, Wr1, bl1);
    gather2<<<(NN * 32 + 255) / 256, 256>>>();
    tc_gemm_l2<<<gemm_blocks, 256>>>(Wl2, Wr2, bl2, batch);
    finalize<<<1, 256>>>(batch, Wout, bout, out);
}

// round 10
// speedup vs baseline: 1.6296x; 1.1514x over previous
#include <cuda_runtime.h>
#include <math.h>

#define NN 100000
#define NE 1000000
#define IN_CH 64
#define HID 128
#define NG 256

#define SCAN_BLOCKS 128
#define SCAN_CH ((NN + SCAN_BLOCKS - 1) / SCAN_BLOCKS)   // 782

// ---------------- scratch (device globals; no allocation) ----------------
__device__ int g_idx64;              // 1 if indices are int64, 0 if int32
__device__ int g_cnt[NN];
__device__ int g_row[NN];
__device__ int g_cur[NN];
__device__ float g_invdeg[NN];
__device__ int g_srcs[NE];
__device__ int g_blocksum[SCAN_BLOCKS];
__device__ __align__(16) float g_agg1[NN * IN_CH];   // 25.6 MB
__device__ __align__(16) float g_agg2[NN * HID];     // 51.2 MB
__device__ __align__(16) float g_h1[NN * HID];       // 51.2 MB
__device__ float g_pooled[NG * HID];

// index accessor honoring detected dtype
__device__ __forceinline__ int getidx(const void* p, long long i) {
    if (g_idx64) return (int)((const long long*)p)[i];
    return ((const int*)p)[i];
}

// ---------------- bf16 helpers ----------------
__device__ __forceinline__ unsigned pack_bf16x2(float lo, float hi) {
    unsigned r;
    asm("cvt.rn.bf16x2.f32 %0, %1, %2;" : "=r"(r) : "f"(hi), "f"(lo));
    return r;
}

__device__ __forceinline__ void mma_bf16(float* c, const unsigned* a, const unsigned* b) {
    asm volatile(
        "mma.sync.aligned.m16n8k16.row.col.f32.bf16.bf16.f32 "
        "{%0,%1,%2,%3},{%4,%5,%6,%7},{%8,%9},{%0,%1,%2,%3};"
        : "+f"(c[0]), "+f"(c[1]), "+f"(c[2]), "+f"(c[3])
        : "r"(a[0]), "r"(a[1]), "r"(a[2]), "r"(a[3]), "r"(b[0]), "r"(b[1]));
}

// convert 8 consecutive floats into 4 packed hi-words + 4 packed lo-words
__device__ __forceinline__ void split_bf16_8(const float* v, unsigned* hp, unsigned* lp) {
#pragma unroll
    for (int j = 0; j < 4; j++) {
        float a0 = v[2 * j], a1 = v[2 * j + 1];
        unsigned h = pack_bf16x2(a0, a1);
        float h0 = __uint_as_float(h << 16);
        float h1 = __uint_as_float(h & 0xffff0000u);
        hp[j] = h;
        lp[j] = pack_bf16x2(a0 - h0, a1 - h1);
    }
}

// ---------------- init: dtype probe + zero counters/pooled (merged) ----------------
__global__ void init_all(const unsigned long long* __restrict__ ei) {
    if (blockIdx.x == 0 && threadIdx.x == 0) {
        int is64 = 1;
        for (int i = 0; i < 16; i++)
            if (ei[i] >> 32) is64 = 0;
        g_idx64 = is64;
    }
    int i = blockIdx.x * blockDim.x + threadIdx.x;
    int stride = gridDim.x * blockDim.x;
    for (int j = i; j < NN; j += stride) g_cnt[j] = 0;
    for (int j = i; j < NG * HID; j += stride) g_pooled[j] = 0.f;
}

// ---------------- histogram of dst degrees ----------------
__global__ void __launch_bounds__(256) hist(const void* __restrict__ ei) {
    int e = blockIdx.x * blockDim.x + threadIdx.x;
    if (e >= NE) return;
    int dst = getidx(ei, NE + e);
    atomicAdd(&g_cnt[dst], 1);
}

// ---------------- 3-phase scan ----------------
__global__ void __launch_bounds__(256) scan_p1() {
    __shared__ int sb[256];
    int b = blockIdx.x, t = threadIdx.x;
    int base = b * SCAN_CH;
    int end = min(base + SCAN_CH, NN);
    int s = 0;
    for (int idx = base + t; idx < end; idx += 256) s += g_cnt[idx];
    sb[t] = s;
    __syncthreads();
    for (int off = 128; off > 0; off >>= 1) {
        if (t < off) sb[t] += sb[t + off];
        __syncthreads();
    }
    if (t == 0) g_blocksum[b] = sb[0];
}

__global__ void __launch_bounds__(128) scan_p2() {
    __shared__ int sb[128];
    int t = threadIdx.x;
    int v = g_blocksum[t];
    sb[t] = v;
    __syncthreads();
    for (int off = 1; off < 128; off <<= 1) {
        int u = (t >= off) ? sb[t - off] : 0;
        __syncthreads();
        sb[t] += u;
        __syncthreads();
    }
    g_blocksum[t] = sb[t] - v;   // exclusive
}

__global__ void __launch_bounds__(256) scan_p3() {
    __shared__ int sb[256];
    __shared__ int s_off;
    int b = blockIdx.x, t = threadIdx.x;
    int base = b * SCAN_CH;
    int end = min(base + SCAN_CH, NN);
    if (t == 0) s_off = g_blocksum[b];
    __syncthreads();
    for (int tile = base; tile < end; tile += 256) {
        int idx = tile + t;
        int c = (idx < end) ? g_cnt[idx] : 0;
        sb[t] = c;
        __syncthreads();
        for (int off = 1; off < 256; off <<= 1) {
            int u = (t >= off) ? sb[t - off] : 0;
            __syncthreads();
            sb[t] += u;
            __syncthreads();
        }
        int incl = sb[t];
        int excl = incl - c;
        if (idx < end) {
            int r = s_off + excl;
            g_row[idx] = r;
            g_cur[idx] = r;
            g_invdeg[idx] = 1.0f / fmaxf((float)c, 1.0f);
        }
        __syncthreads();
        if (t == 255) s_off += sb[255];
        __syncthreads();
    }
}

// ---------------- fill CSR src lists ----------------
__global__ void __launch_bounds__(256) fill_csr(const void* __restrict__ ei) {
    int e = blockIdx.x * blockDim.x + threadIdx.x;
    if (e >= NE) return;
    int dst = getidx(ei, NE + e);
    int src = getidx(ei, e);
    int pos = atomicAdd(&g_cur[dst], 1);
    g_srcs[pos] = src;
}

// ---------------- gather-mean layer 1 (64 ch), 4-way unrolled ----------------
__global__ void __launch_bounds__(256) gather1(const float4* __restrict__ x4) {
    unsigned t = blockIdx.x * blockDim.x + threadIdx.x;
    unsigned n = t >> 4, q = t & 15;
    if (n >= NN) return;
    int start = g_row[n];
    int cnt = g_cnt[n];
    float inv = g_invdeg[n];
    float4 acc = make_float4(0.f, 0.f, 0.f, 0.f);
    int j = 0;
    for (; j + 3 < cnt; j += 4) {
        int s0 = g_srcs[start + j];
        int s1 = g_srcs[start + j + 1];
        int s2 = g_srcs[start + j + 2];
        int s3 = g_srcs[start + j + 3];
        float4 v0 = x4[(size_t)s0 * 16 + q];
        float4 v1 = x4[(size_t)s1 * 16 + q];
        float4 v2 = x4[(size_t)s2 * 16 + q];
        float4 v3 = x4[(size_t)s3 * 16 + q];
        acc.x += v0.x + v1.x + v2.x + v3.x;
        acc.y += v0.y + v1.y + v2.y + v3.y;
        acc.z += v0.z + v1.z + v2.z + v3.z;
        acc.w += v0.w + v1.w + v2.w + v3.w;
    }
    for (; j < cnt; j++) {
        int s = g_srcs[start + j];
        float4 v = x4[(size_t)s * 16 + q];
        acc.x += v.x; acc.y += v.y; acc.z += v.z; acc.w += v.w;
    }
    acc.x *= inv; acc.y *= inv; acc.z *= inv; acc.w *= inv;
    ((float4*)g_agg1)[(size_t)n * 16 + q] = acc;
}

// ---------------- gather-mean layer 2 (128 ch), 4-way unrolled ----------------
__global__ void __launch_bounds__(256) gather2() {
    unsigned t = blockIdx.x * blockDim.x + threadIdx.x;
    unsigned n = t >> 5, q = t & 31;
    if (n >= NN) return;
    int start = g_row[n];
    int cnt = g_cnt[n];
    float inv = g_invdeg[n];
    const float4* h4 = (const float4*)g_h1;
    float4 acc = make_float4(0.f, 0.f, 0.f, 0.f);
    int j = 0;
    for (; j + 3 < cnt; j += 4) {
        int s0 = g_srcs[start + j];
        int s1 = g_srcs[start + j + 1];
        int s2 = g_srcs[start + j + 2];
        int s3 = g_srcs[start + j + 3];
        float4 v0 = h4[(size_t)s0 * 32 + q];
        float4 v1 = h4[(size_t)s1 * 32 + q];
        float4 v2 = h4[(size_t)s2 * 32 + q];
        float4 v3 = h4[(size_t)s3 * 32 + q];
        acc.x += v0.x + v1.x + v2.x + v3.x;
        acc.y += v0.y + v1.y + v2.y + v3.y;
        acc.z += v0.z + v1.z + v2.z + v3.z;
        acc.w += v0.w + v1.w + v2.w + v3.w;
    }
    for (; j < cnt; j++) {
        int s = g_srcs[start + j];
        float4 v = h4[(size_t)s * 32 + q];
        acc.x += v.x; acc.y += v.y; acc.z += v.z; acc.w += v.w;
    }
    acc.x *= inv; acc.y *= inv; acc.z *= inv; acc.w *= inv;
    ((float4*)g_agg2)[(size_t)n * 32 + q] = acc;
}

// ---------------- tensor-core fused SAGE GEMM (3xBF16 m16n8k16) ----------------
// out[n, c] = relu( agg[n] @ W0^T + feat[n] @ W1^T + bias )   (agg pre-normalized)
// Block tile: 128 nodes x 128 ch, 256 threads = 8 warps (4 M x 2 N).
// DO_POOL epilogue: batch is sorted, so a 128-row tile spans <=2 graphs almost
// always -> per-thread bucket sums + warp butterfly reduce + few atomics.
template <int K, bool DO_POOL>
__device__ __forceinline__ void tc_gemm_body(
    const float* __restrict__ agg, const float* __restrict__ feat,
    const float* __restrict__ W0, const float* __restrict__ W1,
    const float* __restrict__ bias, float* __restrict__ out,
    const void* __restrict__ batch) {
    constexpr int KH = K / 2;
    __shared__ unsigned Ah[128][12], Al[128][12];   // [row][kpair]
    __shared__ unsigned Bh[128][12], Bl[128][12];   // [outch][kpair]

    int tid = threadIdx.x;
    int lane = tid & 31, wid = tid >> 5;
    int warpM = wid & 3, warpN = wid >> 2;
    int g = lane >> 2, c = lane & 3;
    int m0 = blockIdx.x * 128;

    int lrow = tid >> 1;             // 0..127
    int lhalf = (tid & 1) * 8;       // float offset 0 or 8
    int lkp = (tid & 1) * 4;         // kpair offset 0 or 4

    float acc[2][8][4];
#pragma unroll
    for (int mt = 0; mt < 2; mt++)
#pragma unroll
        for (int nt = 0; nt < 8; nt++)
#pragma unroll
            for (int i = 0; i < 4; i++) acc[mt][nt][i] = 0.f;

    int node_l = m0 + lrow;
    bool av = node_l < NN;

    float a_reg[8], b_reg[8];
    // ---- load tile 0 into registers ----
    {
        int kg = lhalf;
        float4 v0 = make_float4(0.f, 0.f, 0.f, 0.f), v1 = v0;
        if (av) {
            const float* base = (kg < KH) ? (agg + (size_t)node_l * KH + kg)
                                          : (feat + (size_t)node_l * KH + (kg - KH));
            v0 = *(const float4*)base;
            v1 = *(const float4*)(base + 4);
        }
        a_reg[0] = v0.x; a_reg[1] = v0.y; a_reg[2] = v0.z; a_reg[3] = v0.w;
        a_reg[4] = v1.x; a_reg[5] = v1.y; a_reg[6] = v1.z; a_reg[7] = v1.w;
        const float* wb = (kg < KH) ? (W0 + (size_t)lrow * KH + kg)
                                    : (W1 + (size_t)lrow * KH + (kg - KH));
        float4 w0 = *(const float4*)wb;
        float4 w1 = *(const float4*)(wb + 4);
        b_reg[0] = w0.x; b_reg[1] = w0.y; b_reg[2] = w0.z; b_reg[3] = w0.w;
        b_reg[4] = w1.x; b_reg[5] = w1.y; b_reg[6] = w1.z; b_reg[7] = w1.w;
    }

    for (int kk = 0; kk < K; kk += 16) {
        // ---- convert current regs -> packed bf16 hi/lo in smem ----
        {
            unsigned hp[4], lp[4];
            split_bf16_8(a_reg, hp, lp);
            *(uint4*)&Ah[lrow][lkp] = make_uint4(hp[0], hp[1], hp[2], hp[3]);
            *(uint4*)&Al[lrow][lkp] = make_uint4(lp[0], lp[1], lp[2], lp[3]);
            split_bf16_8(b_reg, hp, lp);
            *(uint4*)&Bh[lrow][lkp] = make_uint4(hp[0], hp[1], hp[2], hp[3]);
            *(uint4*)&Bl[lrow][lkp] = make_uint4(lp[0], lp[1], lp[2], lp[3]);
        }
        __syncthreads();

        // ---- prefetch next tile into registers ----
        if (kk + 16 < K) {
            int kg = kk + 16 + lhalf;
            float4 v0 = make_float4(0.f, 0.f, 0.f, 0.f), v1 = v0;
            if (av) {
                const float* base = (kg < KH) ? (agg + (size_t)node_l * KH + kg)
                                              : (feat + (size_t)node_l * KH + (kg - KH));
                v0 = *(const float4*)base;
                v1 = *(const float4*)(base + 4);
            }
            a_reg[0] = v0.x; a_reg[1] = v0.y; a_reg[2] = v0.z; a_reg[3] = v0.w;
            a_reg[4] = v1.x; a_reg[5] = v1.y; a_reg[6] = v1.z; a_reg[7] = v1.w;
            const float* wb = (kg < KH) ? (W0 + (size_t)lrow * KH + kg)
                                        : (W1 + (size_t)lrow * KH + (kg - KH));
            float4 w0 = *(const float4*)wb;
            float4 w1 = *(const float4*)(wb + 4);
            b_reg[0] = w0.x; b_reg[1] = w0.y; b_reg[2] = w0.z; b_reg[3] = w0.w;
            b_reg[4] = w1.x; b_reg[5] = w1.y; b_reg[6] = w1.z; b_reg[7] = w1.w;
        }

        // ---- compute: one m16n8k16 step covers the whole 16-k tile ----
        {
            unsigned ah[2][4], al[2][4];
#pragma unroll
            for (int mt = 0; mt < 2; mt++) {
                int rb = warpM * 32 + mt * 16;
                ah[mt][0] = Ah[rb + g][c];
                ah[mt][1] = Ah[rb + g + 8][c];
                ah[mt][2] = Ah[rb + g][c + 4];
                ah[mt][3] = Ah[rb + g + 8][c + 4];
                al[mt][0] = Al[rb + g][c];
                al[mt][1] = Al[rb + g + 8][c];
                al[mt][2] = Al[rb + g][c + 4];
                al[mt][3] = Al[rb + g + 8][c + 4];
            }
#pragma unroll
            for (int nt = 0; nt < 8; nt++) {
                int nb = warpN * 64 + nt * 8;
                unsigned bh[2], bl[2];
                bh[0] = Bh[nb + g][c];
                bh[1] = Bh[nb + g][c + 4];
                bl[0] = Bl[nb + g][c];
                bl[1] = Bl[nb + g][c + 4];
#pragma unroll
                for (int mt = 0; mt < 2; mt++) {
                    mma_bf16(acc[mt][nt], ah[mt], bh);   // hi*hi
                    mma_bf16(acc[mt][nt], ah[mt], bl);   // hi*lo
                    mma_bf16(acc[mt][nt], al[mt], bh);   // lo*hi
                }
            }
        }
        __syncthreads();
    }

    // ---- epilogue ----
    if (DO_POOL) {
        int lastrow = min(m0 + 127, NN - 1);
        int g0 = getidx(batch, m0);
        int g1 = getidx(batch, lastrow);
        if (g1 - g0 <= 1) {
            // fast path: block spans at most 2 graphs
            float sumA[16], sumB[16];
#pragma unroll
            for (int k = 0; k < 16; k++) { sumA[k] = 0.f; sumB[k] = 0.f; }
#pragma unroll
            for (int mt = 0; mt < 2; mt++) {
                int r0 = m0 + warpM * 32 + mt * 16 + g;
                int r1 = r0 + 8;
                int gr0 = (r0 < NN) ? getidx(batch, r0) : -1;
                int gr1 = (r1 < NN) ? getidx(batch, r1) : -1;
#pragma unroll
                for (int nt = 0; nt < 8; nt++) {
                    int col = warpN * 64 + nt * 8 + 2 * c;
                    float b0 = bias[col], b1 = bias[col + 1];
                    float v00 = fmaxf(acc[mt][nt][0] + b0, 0.f);
                    float v01 = fmaxf(acc[mt][nt][1] + b1, 0.f);
                    float v10 = fmaxf(acc[mt][nt][2] + b0, 0.f);
                    float v11 = fmaxf(acc[mt][nt][3] + b1, 0.f);
                    if (gr0 == g0) { sumA[nt * 2] += v00; sumA[nt * 2 + 1] += v01; }
                    else if (gr0 > g0) { sumB[nt * 2] += v00; sumB[nt * 2 + 1] += v01; }
                    if (gr1 == g0) { sumA[nt * 2] += v10; sumA[nt * 2 + 1] += v11; }
                    else if (gr1 > g0) { sumB[nt * 2] += v10; sumB[nt * 2 + 1] += v11; }
                }
            }
            // butterfly reduce over the 8 row-groups (g) within the warp
#pragma unroll
            for (int k = 0; k < 16; k++) {
#pragma unroll
                for (int off = 4; off <= 16; off <<= 1) {
                    sumA[k] += __shfl_xor_sync(0xffffffffu, sumA[k], off);
                    sumB[k] += __shfl_xor_sync(0xffffffffu, sumB[k], off);
                }
            }
            if (g == 0) {   // lanes 0..3 hold full warp sums
#pragma unroll
                for (int nt = 0; nt < 8; nt++) {
                    int col = warpN * 64 + nt * 8 + 2 * c;
                    atomicAdd(&g_pooled[(size_t)g0 * HID + col], sumA[nt * 2]);
                    atomicAdd(&g_pooled[(size_t)g0 * HID + col + 1], sumA[nt * 2 + 1]);
                    if (g1 != g0) {
                        atomicAdd(&g_pooled[(size_t)g1 * HID + col], sumB[nt * 2]);
                        atomicAdd(&g_pooled[(size_t)g1 * HID + col + 1], sumB[nt * 2 + 1]);
                    }
                }
            }
        } else {
            // fallback: per-row atomics
#pragma unroll
            for (int mt = 0; mt < 2; mt++) {
                int r0 = m0 + warpM * 32 + mt * 16 + g;
                int r1 = r0 + 8;
#pragma unroll
                for (int nt = 0; nt < 8; nt++) {
                    int col = warpN * 64 + nt * 8 + 2 * c;
                    float b0 = bias[col], b1 = bias[col + 1];
                    float v00 = fmaxf(acc[mt][nt][0] + b0, 0.f);
                    float v01 = fmaxf(acc[mt][nt][1] + b1, 0.f);
                    float v10 = fmaxf(acc[mt][nt][2] + b0, 0.f);
                    float v11 = fmaxf(acc[mt][nt][3] + b1, 0.f);
                    if (r0 < NN) {
                        float* p = g_pooled + (size_t)getidx(batch, r0) * HID + col;
                        atomicAdd(p, v00);
                        atomicAdd(p + 1, v01);
                    }
                    if (r1 < NN) {
                        float* p = g_pooled + (size_t)getidx(batch, r1) * HID + col;
                        atomicAdd(p, v10);
                        atomicAdd(p + 1, v11);
                    }
                }
            }
        }
    } else {
#pragma unroll
        for (int mt = 0; mt < 2; mt++) {
            int r0 = m0 + warpM * 32 + mt * 16 + g;
            int r1 = r0 + 8;
#pragma unroll
            for (int nt = 0; nt < 8; nt++) {
                int col = warpN * 64 + nt * 8 + 2 * c;
                float b0 = bias[col], b1 = bias[col + 1];
                float v00 = fmaxf(acc[mt][nt][0] + b0, 0.f);
                float v01 = fmaxf(acc[mt][nt][1] + b1, 0.f);
                float v10 = fmaxf(acc[mt][nt][2] + b0, 0.f);
                float v11 = fmaxf(acc[mt][nt][3] + b1, 0.f);
                if (r0 < NN) *(float2*)(out + (size_t)r0 * HID + col) = make_float2(v00, v01);
                if (r1 < NN) *(float2*)(out + (size_t)r1 * HID + col) = make_float2(v10, v11);
            }
        }
    }
}

__global__ void __launch_bounds__(256) tc_gemm_l1(
    const float* __restrict__ x, const float* __restrict__ W0,
    const float* __restrict__ W1, const float* __restrict__ bias) {
    tc_gemm_body<2 * IN_CH, false>(g_agg1, x, W0, W1, bias, g_h1, nullptr);
}

__global__ void __launch_bounds__(256) tc_gemm_l2(
    const float* __restrict__ W0, const float* __restrict__ W1,
    const float* __restrict__ bias, const void* __restrict__ batch) {
    tc_gemm_body<2 * HID, true>(g_agg2, g_h1, W0, W1, bias, nullptr, batch);
}

// ---------------- finalize: per-graph mean, Wout, log_softmax ----------------
__global__ void __launch_bounds__(256) finalize(const void* __restrict__ batch,
                                                const float* __restrict__ Wout,
                                                const float* __restrict__ bout,
                                                float* __restrict__ outp) {
    int g = threadIdx.x;
    auto lower_bound = [&](int v) {
        int lo = 0, hi = NN;
        while (lo < hi) {
            int mid = (lo + hi) >> 1;
            if (getidx(batch, mid) < v) lo = mid + 1; else hi = mid;
        }
        return lo;
    };
    int cnt = lower_bound(g + 1) - lower_bound(g);
    float inv = 1.0f / fmaxf((float)cnt, 1.0f);
    float l0 = bout[0], l1 = bout[1];
    for (int c = 0; c < HID; c++) {
        float p = g_pooled[(size_t)g * HID + c] * inv;
        l0 += p * Wout[c];
        l1 += p * Wout[HID + c];
    }
    float m = fmaxf(l0, l1);
    float lse = m + logf(expf(l0 - m) + expf(l1 - m));
    outp[g * 2 + 0] = l0 - lse;
    outp[g * 2 + 1] = l1 - lse;
}

// ---------------- launch ----------------
extern "C" void kernel_launch(void* const* d_in, const int* in_sizes, int n_in,
                              void* d_out, int out_size) {
    const float* x = (const float*)d_in[0];
    const void* ei = d_in[1];
    const void* batch = d_in[2];
    const float* Wl1 = (const float*)d_in[3];
    const float* bl1 = (const float*)d_in[4];
    const float* Wr1 = (const float*)d_in[5];
    const float* Wl2 = (const float*)d_in[6];
    const float* bl2 = (const float*)d_in[7];
    const float* Wr2 = (const float*)d_in[8];
    const float* Wout = (const float*)d_in[9];
    const float* bout = (const float*)d_in[10];
    float* out = (float*)d_out;

    int eb = (NE + 255) / 256;
    int gemm_blocks = (NN + 127) / 128;

    init_all<<<256, 256>>>((const unsigned long long*)ei);
    hist<<<eb, 256>>>(ei);
    scan_p1<<<SCAN_BLOCKS, 256>>>();
    scan_p2<<<1, 128>>>();
    scan_p3<<<SCAN_BLOCKS, 256>>>();
    fill_csr<<<eb, 256>>>(ei);

    gather1<<<(NN * 16 + 255) / 256, 256>>>((const float4*)x);
    tc_gemm_l1<<<gemm_blocks, 256>>>(x, Wl1, Wr1, bl1);
    gather2<<<(NN * 32 + 255) / 256, 256>>>();
    tc_gemm_l2<<<gemm_blocks, 256>>>(Wl2, Wr2, bl2, batch);
    finalize<<<1, 256>>>(batch, Wout, bout, out);
}

// round 11
// speedup vs baseline: 1.6828x; 1.0326x over previous
#include <cuda_runtime.h>
#include <math.h>

#define NN 100000
#define NE 1000000
#define IN_CH 64
#define HID 128
#define NG 256

#define SCAN_BLOCKS 128
#define SCAN_CH ((NN + SCAN_BLOCKS - 1) / SCAN_BLOCKS)   // 782

// ---------------- scratch (device globals; no allocation) ----------------
__device__ int g_idx64;              // 1 if indices are int64, 0 if int32
__device__ int g_cnt[NN];
__device__ int g_row[NN];
__device__ int g_cur[NN];
__device__ float g_invdeg[NN];
__device__ int g_srcs[NE];
__device__ int g_blocksum[SCAN_BLOCKS];
__device__ __align__(16) float g_agg1[NN * IN_CH];   // 25.6 MB
__device__ __align__(16) float g_agg2[NN * HID];     // 51.2 MB
__device__ __align__(16) float g_h1[NN * HID];       // 51.2 MB
__device__ float g_pooled[NG * HID];
// pre-split weights: packed bf16x2 pairs along k, [outch][K/2]
__device__ __align__(16) unsigned g_Wh1[HID * IN_CH];    // K=128 -> 64 pairs
__device__ __align__(16) unsigned g_Wl1[HID * IN_CH];
__device__ __align__(16) unsigned g_Wh2[HID * HID];      // K=256 -> 128 pairs
__device__ __align__(16) unsigned g_Wl2[HID * HID];

// index accessor honoring detected dtype
__device__ __forceinline__ int getidx(const void* p, long long i) {
    if (g_idx64) return (int)((const long long*)p)[i];
    return ((const int*)p)[i];
}

// ---------------- bf16 helpers ----------------
__device__ __forceinline__ unsigned pack_bf16x2(float lo, float hi) {
    unsigned r;
    asm("cvt.rn.bf16x2.f32 %0, %1, %2;" : "=r"(r) : "f"(hi), "f"(lo));
    return r;
}

__device__ __forceinline__ void mma_bf16(float* c, const unsigned* a, const unsigned* b) {
    asm volatile(
        "mma.sync.aligned.m16n8k16.row.col.f32.bf16.bf16.f32 "
        "{%0,%1,%2,%3},{%4,%5,%6,%7},{%8,%9},{%0,%1,%2,%3};"
        : "+f"(c[0]), "+f"(c[1]), "+f"(c[2]), "+f"(c[3])
        : "r"(a[0]), "r"(a[1]), "r"(a[2]), "r"(a[3]), "r"(b[0]), "r"(b[1]));
}

__device__ __forceinline__ void ldsm_x4(unsigned& r0, unsigned& r1, unsigned& r2, unsigned& r3,
                                        unsigned addr) {
    asm volatile("ldmatrix.sync.aligned.m8n8.x4.shared.b16 {%0,%1,%2,%3}, [%4];"
                 : "=r"(r0), "=r"(r1), "=r"(r2), "=r"(r3) : "r"(addr));
}

__device__ __forceinline__ void ldsm_x2(unsigned& r0, unsigned& r1, unsigned addr) {
    asm volatile("ldmatrix.sync.aligned.m8n8.x2.shared.b16 {%0,%1}, [%2];"
                 : "=r"(r0), "=r"(r1) : "r"(addr));
}

// convert 8 consecutive floats into 4 packed hi-words + 4 packed lo-words
__device__ __forceinline__ void split_bf16_8(const float* v, unsigned* hp, unsigned* lp) {
#pragma unroll
    for (int j = 0; j < 4; j++) {
        float a0 = v[2 * j], a1 = v[2 * j + 1];
        unsigned h = pack_bf16x2(a0, a1);
        float h0 = __uint_as_float(h << 16);
        float h1 = __uint_as_float(h & 0xffff0000u);
        hp[j] = h;
        lp[j] = pack_bf16x2(a0 - h0, a1 - h1);
    }
}

// ---------------- init: dtype probe + zero counters/pooled (merged) ----------------
__global__ void init_all(const unsigned long long* __restrict__ ei) {
    if (blockIdx.x == 0 && threadIdx.x == 0) {
        int is64 = 1;
        for (int i = 0; i < 16; i++)
            if (ei[i] >> 32) is64 = 0;
        g_idx64 = is64;
    }
    int i = blockIdx.x * blockDim.x + threadIdx.x;
    int stride = gridDim.x * blockDim.x;
    for (int j = i; j < NN; j += stride) g_cnt[j] = 0;
    for (int j = i; j < NG * HID; j += stride) g_pooled[j] = 0.f;
}

// ---------------- pre-split weights into packed bf16 hi/lo ----------------
// layer1: B = [Wl1 | Wr1], KH=64 each -> 64 pairs/row
// layer2: B = [Wl2 | Wr2], KH=128 each -> 128 pairs/row
__global__ void __launch_bounds__(256) split_weights(
    const float* __restrict__ Wl1, const float* __restrict__ Wr1,
    const float* __restrict__ Wl2, const float* __restrict__ Wr2) {
    int idx = blockIdx.x * blockDim.x + threadIdx.x;
    const int P1 = HID * IN_CH;          // layer1 pairs total (128*64)
    const int P2 = HID * HID;            // layer2 pairs total (128*128)
    if (idx < P1) {
        const int PPR = IN_CH;           // pairs per row = K/2 = 64
        int row = idx / PPR, p = idx % PPR;
        int k0 = 2 * p;
        const int KH = IN_CH;            // 64
        float v0 = (k0 < KH) ? Wl1[row * KH + k0] : Wr1[row * KH + k0 - KH];
        float v1 = (k0 < KH) ? Wl1[row * KH + k0 + 1] : Wr1[row * KH + k0 + 1 - KH];
        unsigned h = pack_bf16x2(v0, v1);
        float h0 = __uint_as_float(h << 16);
        float h1 = __uint_as_float(h & 0xffff0000u);
        g_Wh1[idx] = h;
        g_Wl1[idx] = pack_bf16x2(v0 - h0, v1 - h1);
    } else if (idx < P1 + P2) {
        int j = idx - P1;
        const int PPR = HID;             // pairs per row = 128
        int row = j / PPR, p = j % PPR;
        int k0 = 2 * p;
        const int KH = HID;              // 128
        float v0 = (k0 < KH) ? Wl2[row * KH + k0] : Wr2[row * KH + k0 - KH];
        float v1 = (k0 < KH) ? Wl2[row * KH + k0 + 1] : Wr2[row * KH + k0 + 1 - KH];
        unsigned h = pack_bf16x2(v0, v1);
        float h0 = __uint_as_float(h << 16);
        float h1 = __uint_as_float(h & 0xffff0000u);
        g_Wh2[j] = h;
        g_Wl2[j] = pack_bf16x2(v0 - h0, v1 - h1);
    }
}

// ---------------- histogram of dst degrees ----------------
__global__ void __launch_bounds__(256) hist(const void* __restrict__ ei) {
    int e = blockIdx.x * blockDim.x + threadIdx.x;
    if (e >= NE) return;
    int dst = getidx(ei, NE + e);
    atomicAdd(&g_cnt[dst], 1);
}

// ---------------- 3-phase scan ----------------
__global__ void __launch_bounds__(256) scan_p1() {
    __shared__ int sb[256];
    int b = blockIdx.x, t = threadIdx.x;
    int base = b * SCAN_CH;
    int end = min(base + SCAN_CH, NN);
    int s = 0;
    for (int idx = base + t; idx < end; idx += 256) s += g_cnt[idx];
    sb[t] = s;
    __syncthreads();
    for (int off = 128; off > 0; off >>= 1) {
        if (t < off) sb[t] += sb[t + off];
        __syncthreads();
    }
    if (t == 0) g_blocksum[b] = sb[0];
}

__global__ void __launch_bounds__(128) scan_p2() {
    __shared__ int sb[128];
    int t = threadIdx.x;
    int v = g_blocksum[t];
    sb[t] = v;
    __syncthreads();
    for (int off = 1; off < 128; off <<= 1) {
        int u = (t >= off) ? sb[t - off] : 0;
        __syncthreads();
        sb[t] += u;
        __syncthreads();
    }
    g_blocksum[t] = sb[t] - v;   // exclusive
}

__global__ void __launch_bounds__(256) scan_p3() {
    __shared__ int sb[256];
    __shared__ int s_off;
    int b = blockIdx.x, t = threadIdx.x;
    int base = b * SCAN_CH;
    int end = min(base + SCAN_CH, NN);
    if (t == 0) s_off = g_blocksum[b];
    __syncthreads();
    for (int tile = base; tile < end; tile += 256) {
        int idx = tile + t;
        int c = (idx < end) ? g_cnt[idx] : 0;
        sb[t] = c;
        __syncthreads();
        for (int off = 1; off < 256; off <<= 1) {
            int u = (t >= off) ? sb[t - off] : 0;
            __syncthreads();
            sb[t] += u;
            __syncthreads();
        }
        int incl = sb[t];
        int excl = incl - c;
        if (idx < end) {
            int r = s_off + excl;
            g_row[idx] = r;
            g_cur[idx] = r;
            g_invdeg[idx] = 1.0f / fmaxf((float)c, 1.0f);
        }
        __syncthreads();
        if (t == 255) s_off += sb[255];
        __syncthreads();
    }
}

// ---------------- fill CSR src lists ----------------
__global__ void __launch_bounds__(256) fill_csr(const void* __restrict__ ei) {
    int e = blockIdx.x * blockDim.x + threadIdx.x;
    if (e >= NE) return;
    int dst = getidx(ei, NE + e);
    int src = getidx(ei, e);
    int pos = atomicAdd(&g_cur[dst], 1);
    g_srcs[pos] = src;
}

// ---------------- gather-mean layer 1 (64 ch), 4-way unrolled ----------------
__global__ void __launch_bounds__(256) gather1(const float4* __restrict__ x4) {
    unsigned t = blockIdx.x * blockDim.x + threadIdx.x;
    unsigned n = t >> 4, q = t & 15;
    if (n >= NN) return;
    int start = g_row[n];
    int cnt = g_cnt[n];
    float inv = g_invdeg[n];
    float4 acc = make_float4(0.f, 0.f, 0.f, 0.f);
    int j = 0;
    for (; j + 3 < cnt; j += 4) {
        int s0 = g_srcs[start + j];
        int s1 = g_srcs[start + j + 1];
        int s2 = g_srcs[start + j + 2];
        int s3 = g_srcs[start + j + 3];
        float4 v0 = x4[(size_t)s0 * 16 + q];
        float4 v1 = x4[(size_t)s1 * 16 + q];
        float4 v2 = x4[(size_t)s2 * 16 + q];
        float4 v3 = x4[(size_t)s3 * 16 + q];
        acc.x += v0.x + v1.x + v2.x + v3.x;
        acc.y += v0.y + v1.y + v2.y + v3.y;
        acc.z += v0.z + v1.z + v2.z + v3.z;
        acc.w += v0.w + v1.w + v2.w + v3.w;
    }
    for (; j < cnt; j++) {
        int s = g_srcs[start + j];
        float4 v = x4[(size_t)s * 16 + q];
        acc.x += v.x; acc.y += v.y; acc.z += v.z; acc.w += v.w;
    }
    acc.x *= inv; acc.y *= inv; acc.z *= inv; acc.w *= inv;
    ((float4*)g_agg1)[(size_t)n * 16 + q] = acc;
}

// ---------------- gather-mean layer 2 (128 ch), 4-way unrolled ----------------
__global__ void __launch_bounds__(256) gather2() {
    unsigned t = blockIdx.x * blockDim.x + threadIdx.x;
    unsigned n = t >> 5, q = t & 31;
    if (n >= NN) return;
    int start = g_row[n];
    int cnt = g_cnt[n];
    float inv = g_invdeg[n];
    const float4* h4 = (const float4*)g_h1;
    float4 acc = make_float4(0.f, 0.f, 0.f, 0.f);
    int j = 0;
    for (; j + 3 < cnt; j += 4) {
        int s0 = g_srcs[start + j];
        int s1 = g_srcs[start + j + 1];
        int s2 = g_srcs[start + j + 2];
        int s3 = g_srcs[start + j + 3];
        float4 v0 = h4[(size_t)s0 * 32 + q];
        float4 v1 = h4[(size_t)s1 * 32 + q];
        float4 v2 = h4[(size_t)s2 * 32 + q];
        float4 v3 = h4[(size_t)s3 * 32 + q];
        acc.x += v0.x + v1.x + v2.x + v3.x;
        acc.y += v0.y + v1.y + v2.y + v3.y;
        acc.z += v0.z + v1.z + v2.z + v3.z;
        acc.w += v0.w + v1.w + v2.w + v3.w;
    }
    for (; j < cnt; j++) {
        int s = g_srcs[start + j];
        float4 v = h4[(size_t)s * 32 + q];
        acc.x += v.x; acc.y += v.y; acc.z += v.z; acc.w += v.w;
    }
    acc.x *= inv; acc.y *= inv; acc.z *= inv; acc.w *= inv;
    ((float4*)g_agg2)[(size_t)n * 32 + q] = acc;
}

// ---------------- tensor-core fused SAGE GEMM (3xBF16 m16n8k16 + ldmatrix) ----------------
// out[n, c] = relu( agg[n] @ W0^T + feat[n] @ W1^T + bias )   (agg pre-normalized)
// Block tile: 128 nodes x 128 ch, 256 threads = 8 warps (4 M x 2 N).
// A converted to bf16 hi/lo at tile load; B pre-split in gmem (packed uint).
// Fragment loads via ldmatrix (48B row stride -> conflict-free phases).
template <int K, bool DO_POOL>
__device__ __forceinline__ void tc_gemm_body(
    const float* __restrict__ agg, const float* __restrict__ feat,
    const unsigned* __restrict__ Wh, const unsigned* __restrict__ Wl,
    const float* __restrict__ bias, float* __restrict__ out,
    const void* __restrict__ batch) {
    constexpr int KH = K / 2;
    constexpr int PPR = K / 2;           // weight pairs per row
    __shared__ unsigned Ah[128][12], Al[128][12];   // [row][kpair], 48B stride
    __shared__ unsigned Bh[128][12], Bl[128][12];   // [outch][kpair]

    int tid = threadIdx.x;
    int lane = tid & 31, wid = tid >> 5;
    int warpM = wid & 3, warpN = wid >> 2;
    int g = lane >> 2, c = lane & 3;
    int m0 = blockIdx.x * 128;

    int lrow = tid >> 1;             // 0..127
    int lhalf = (tid & 1) * 8;       // float offset 0 or 8
    int lkp = (tid & 1) * 4;         // kpair offset 0 or 4

    // ---- ldmatrix addresses (constant across tiles) ----
    unsigned AhB = (unsigned)__cvta_generic_to_shared(&Ah[0][0]);
    unsigned AlB = (unsigned)__cvta_generic_to_shared(&Al[0][0]);
    unsigned BhB = (unsigned)__cvta_generic_to_shared(&Bh[0][0]);
    unsigned BlB = (unsigned)__cvta_generic_to_shared(&Bl[0][0]);
    int arow = (lane & 7) + (lane & 8);          // row within m16 tile
    unsigned acol = (lane & 16) ? 16u : 0u;      // k-half byte offset
    unsigned aoff0 = (unsigned)(warpM * 32 + arow) * 48u + acol;
    unsigned aoff1 = aoff0 + 16u * 48u;          // second m16 tile
    unsigned boff = (unsigned)(warpN * 64 + (lane & 7)) * 48u + ((lane & 8) ? 16u : 0u);

    float acc[2][8][4];
#pragma unroll
    for (int mt = 0; mt < 2; mt++)
#pragma unroll
        for (int nt = 0; nt < 8; nt++)
#pragma unroll
            for (int i = 0; i < 4; i++) acc[mt][nt][i] = 0.f;

    int node_l = m0 + lrow;
    bool av = node_l < NN;

    float a_reg[8];
    uint4 wh_reg, wl_reg;
    // ---- load tile 0 into registers ----
    {
        int kg = lhalf;
        float4 v0 = make_float4(0.f, 0.f, 0.f, 0.f), v1 = v0;
        if (av) {
            const float* base = (kg < KH) ? (agg + (size_t)node_l * KH + kg)
                                          : (feat + (size_t)node_l * KH + (kg - KH));
            v0 = *(const float4*)base;
            v1 = *(const float4*)(base + 4);
        }
        a_reg[0] = v0.x; a_reg[1] = v0.y; a_reg[2] = v0.z; a_reg[3] = v0.w;
        a_reg[4] = v1.x; a_reg[5] = v1.y; a_reg[6] = v1.z; a_reg[7] = v1.w;
        wh_reg = *(const uint4*)(Wh + (size_t)lrow * PPR + lkp);
        wl_reg = *(const uint4*)(Wl + (size_t)lrow * PPR + lkp);
    }

    for (int kk = 0; kk < K; kk += 16) {
        // ---- convert A regs -> packed bf16 hi/lo; store B regs directly ----
        {
            unsigned hp[4], lp[4];
            split_bf16_8(a_reg, hp, lp);
            *(uint4*)&Ah[lrow][lkp] = make_uint4(hp[0], hp[1], hp[2], hp[3]);
            *(uint4*)&Al[lrow][lkp] = make_uint4(lp[0], lp[1], lp[2], lp[3]);
            *(uint4*)&Bh[lrow][lkp] = wh_reg;
            *(uint4*)&Bl[lrow][lkp] = wl_reg;
        }
        __syncthreads();

        // ---- prefetch next tile into registers ----
        if (kk + 16 < K) {
            int kg = kk + 16 + lhalf;
            float4 v0 = make_float4(0.f, 0.f, 0.f, 0.f), v1 = v0;
            if (av) {
                const float* base = (kg < KH) ? (agg + (size_t)node_l * KH + kg)
                                              : (feat + (size_t)node_l * KH + (kg - KH));
                v0 = *(const float4*)base;
                v1 = *(const float4*)(base + 4);
            }
            a_reg[0] = v0.x; a_reg[1] = v0.y; a_reg[2] = v0.z; a_reg[3] = v0.w;
            a_reg[4] = v1.x; a_reg[5] = v1.y; a_reg[6] = v1.z; a_reg[7] = v1.w;
            int pbase = (kk + 16) / 2 + lkp;
            wh_reg = *(const uint4*)(Wh + (size_t)lrow * PPR + pbase);
            wl_reg = *(const uint4*)(Wl + (size_t)lrow * PPR + pbase);
        }

        // ---- compute: ldmatrix fragment loads + MMA ----
        {
            unsigned ah[2][4], al[2][4];
            ldsm_x4(ah[0][0], ah[0][1], ah[0][2], ah[0][3], AhB + aoff0);
            ldsm_x4(ah[1][0], ah[1][1], ah[1][2], ah[1][3], AhB + aoff1);
            ldsm_x4(al[0][0], al[0][1], al[0][2], al[0][3], AlB + aoff0);
            ldsm_x4(al[1][0], al[1][1], al[1][2], al[1][3], AlB + aoff1);
#pragma unroll
            for (int nt = 0; nt < 8; nt++) {
                unsigned bh[2], bl[2];
                ldsm_x2(bh[0], bh[1], BhB + boff + nt * 384u);
                ldsm_x2(bl[0], bl[1], BlB + boff + nt * 384u);
#pragma unroll
                for (int mt = 0; mt < 2; mt++) {
                    mma_bf16(acc[mt][nt], ah[mt], bh);   // hi*hi
                    mma_bf16(acc[mt][nt], ah[mt], bl);   // hi*lo
                    mma_bf16(acc[mt][nt], al[mt], bh);   // lo*hi
                }
            }
        }
        __syncthreads();
    }

    // ---- epilogue ----
    if (DO_POOL) {
        int lastrow = min(m0 + 127, NN - 1);
        int g0 = getidx(batch, m0);
        int g1 = getidx(batch, lastrow);
        if (g1 - g0 <= 1) {
            // fast path: block spans at most 2 graphs
            float sumA[16], sumB[16];
#pragma unroll
            for (int k = 0; k < 16; k++) { sumA[k] = 0.f; sumB[k] = 0.f; }
#pragma unroll
            for (int mt = 0; mt < 2; mt++) {
                int r0 = m0 + warpM * 32 + mt * 16 + g;
                int r1 = r0 + 8;
                int gr0 = (r0 < NN) ? getidx(batch, r0) : -1;
                int gr1 = (r1 < NN) ? getidx(batch, r1) : -1;
#pragma unroll
                for (int nt = 0; nt < 8; nt++) {
                    int col = warpN * 64 + nt * 8 + 2 * c;
                    float b0 = bias[col], b1 = bias[col + 1];
                    float v00 = fmaxf(acc[mt][nt][0] + b0, 0.f);
                    float v01 = fmaxf(acc[mt][nt][1] + b1, 0.f);
                    float v10 = fmaxf(acc[mt][nt][2] + b0, 0.f);
                    float v11 = fmaxf(acc[mt][nt][3] + b1, 0.f);
                    if (gr0 == g0) { sumA[nt * 2] += v00; sumA[nt * 2 + 1] += v01; }
                    else if (gr0 > g0) { sumB[nt * 2] += v00; sumB[nt * 2 + 1] += v01; }
                    if (gr1 == g0) { sumA[nt * 2] += v10; sumA[nt * 2 + 1] += v11; }
                    else if (gr1 > g0) { sumB[nt * 2] += v10; sumB[nt * 2 + 1] += v11; }
                }
            }
            // butterfly reduce over the 8 row-groups (g) within the warp
#pragma unroll
            for (int k = 0; k < 16; k++) {
#pragma unroll
                for (int off = 4; off <= 16; off <<= 1) {
                    sumA[k] += __shfl_xor_sync(0xffffffffu, sumA[k], off);
                    sumB[k] += __shfl_xor_sync(0xffffffffu, sumB[k], off);
                }
            }
            if (g == 0) {   // lanes 0..3 hold full warp sums
#pragma unroll
                for (int nt = 0; nt < 8; nt++) {
                    int col = warpN * 64 + nt * 8 + 2 * c;
                    atomicAdd(&g_pooled[(size_t)g0 * HID + col], sumA[nt * 2]);
                    atomicAdd(&g_pooled[(size_t)g0 * HID + col + 1], sumA[nt * 2 + 1]);
                    if (g1 != g0) {
                        atomicAdd(&g_pooled[(size_t)g1 * HID + col], sumB[nt * 2]);
                        atomicAdd(&g_pooled[(size_t)g1 * HID + col + 1], sumB[nt * 2 + 1]);
                    }
                }
            }
        } else {
            // fallback: per-row atomics
#pragma unroll
            for (int mt = 0; mt < 2; mt++) {
                int r0 = m0 + warpM * 32 + mt * 16 + g;
                int r1 = r0 + 8;
#pragma unroll
                for (int nt = 0; nt < 8; nt++) {
                    int col = warpN * 64 + nt * 8 + 2 * c;
                    float b0 = bias[col], b1 = bias[col + 1];
                    float v00 = fmaxf(acc[mt][nt][0] + b0, 0.f);
                    float v01 = fmaxf(acc[mt][nt][1] + b1, 0.f);
                    float v10 = fmaxf(acc[mt][nt][2] + b0, 0.f);
                    float v11 = fmaxf(acc[mt][nt][3] + b1, 0.f);
                    if (r0 < NN) {
                        float* p = g_pooled + (size_t)getidx(batch, r0) * HID + col;
                        atomicAdd(p, v00);
                        atomicAdd(p + 1, v01);
                    }
                    if (r1 < NN) {
                        float* p = g_pooled + (size_t)getidx(batch, r1) * HID + col;
                        atomicAdd(p, v10);
                        atomicAdd(p + 1, v11);
                    }
                }
            }
        }
    } else {
#pragma unroll
        for (int mt = 0; mt < 2; mt++) {
            int r0 = m0 + warpM * 32 + mt * 16 + g;
            int r1 = r0 + 8;
#pragma unroll
            for (int nt = 0; nt < 8; nt++) {
                int col = warpN * 64 + nt * 8 + 2 * c;
                float b0 = bias[col], b1 = bias[col + 1];
                float v00 = fmaxf(acc[mt][nt][0] + b0, 0.f);
                float v01 = fmaxf(acc[mt][nt][1] + b1, 0.f);
                float v10 = fmaxf(acc[mt][nt][2] + b0, 0.f);
                float v11 = fmaxf(acc[mt][nt][3] + b1, 0.f);
                if (r0 < NN) *(float2*)(out + (size_t)r0 * HID + col) = make_float2(v00, v01);
                if (r1 < NN) *(float2*)(out + (size_t)r1 * HID + col) = make_float2(v10, v11);
            }
        }
    }
}

__global__ void __launch_bounds__(256) tc_gemm_l1(
    const float* __restrict__ x, const float* __restrict__ bias) {
    tc_gemm_body<2 * IN_CH, false>(g_agg1, x, g_Wh1, g_Wl1, bias, g_h1, nullptr);
}

__global__ void __launch_bounds__(256) tc_gemm_l2(
    const float* __restrict__ bias, const void* __restrict__ batch) {
    tc_gemm_body<2 * HID, true>(g_agg2, g_h1, g_Wh2, g_Wl2, bias, nullptr, batch);
}

// ---------------- finalize: per-graph mean, Wout, log_softmax ----------------
__global__ void __launch_bounds__(256) finalize(const void* __restrict__ batch,
                                                const float* __restrict__ Wout,
                                                const float* __restrict__ bout,
                                                float* __restrict__ outp) {
    int g = threadIdx.x;
    auto lower_bound = [&](int v) {
        int lo = 0, hi = NN;
        while (lo < hi) {
            int mid = (lo + hi) >> 1;
            if (getidx(batch, mid) < v) lo = mid + 1; else hi = mid;
        }
        return lo;
    };
    int cnt = lower_bound(g + 1) - lower_bound(g);
    float inv = 1.0f / fmaxf((float)cnt, 1.0f);
    float l0 = bout[0], l1 = bout[1];
    for (int c = 0; c < HID; c++) {
        float p = g_pooled[(size_t)g * HID + c] * inv;
        l0 += p * Wout[c];
        l1 += p * Wout[HID + c];
    }
    float m = fmaxf(l0, l1);
    float lse = m + logf(expf(l0 - m) + expf(l1 - m));
    outp[g * 2 + 0] = l0 - lse;
    outp[g * 2 + 1] = l1 - lse;
}

// ---------------- launch ----------------
extern "C" void kernel_launch(void* const* d_in, const int* in_sizes, int n_in,
                              void* d_out, int out_size) {
    const float* x = (const float*)d_in[0];
    const void* ei = d_in[1];
    const void* batch = d_in[2];
    const float* Wl1 = (const float*)d_in[3];
    const float* bl1 = (const float*)d_in[4];
    const float* Wr1 = (const float*)d_in[5];
    const float* Wl2 = (const float*)d_in[6];
    const float* bl2 = (const float*)d_in[7];
    const float* Wr2 = (const float*)d_in[8];
    const float* Wout = (const float*)d_in[9];
    const float* bout = (const float*)d_in[10];
    float* out = (float*)d_out;

    int eb = (NE + 255) / 256;
    int gemm_blocks = (NN + 127) / 128;
    int wsplit_total = HID * IN_CH + HID * HID;   // 24576

    init_all<<<256, 256>>>((const unsigned long long*)ei);
    split_weights<<<(wsplit_total + 255) / 256, 256>>>(Wl1, Wr1, Wl2, Wr2);
    hist<<<eb, 256>>>(ei);
    scan_p1<<<SCAN_BLOCKS, 256>>>();
    scan_p2<<<1, 128>>>();
    scan_p3<<<SCAN_BLOCKS, 256>>>();
    fill_csr<<<eb, 256>>>(ei);

    gather1<<<(NN * 16 + 255) / 256, 256>>>((const float4*)x);
    tc_gemm_l1<<<gemm_blocks, 256>>>(x, bl1);
    gather2<<<(NN * 32 + 255) / 256, 256>>>();
    tc_gemm_l2<<<gemm_blocks, 256>>>(bl2, batch);
    finalize<<<1, 256>>>(batch, Wout, bout, out);
}